// round 5
// baseline (speedup 1.0000x reference)
#include <cuda_runtime.h>

// Problem constants
#define NN 100000
#define EE 1600000

// ---------------- scratch (device globals; no allocation allowed) ----------
__device__ __align__(16) float g_ae2[EE * 4];    // layer-2 edge logit term   (25.6 MB)
__device__ __align__(16) float g_xp[NN * 64];    // per-node projected feats  (25.6 MB)
__device__ __align__(16) float g_acc[NN * 64];   // weighted aggregation      (25.6 MB)
__device__ float g_asrc[NN * 4];
__device__ float g_adst[NN * 4];
__device__ float g_denom[NN * 4];
__device__ float g_P[512];                        // folded [64][8]: cols 0-3 L1, 4-7 L2

// ---------------------------------------------------------------------------
// edge_index dtype hedge: reference says int64, harness doc says int32.
// For int64 data (all values < 2^31, little-endian) the odd 32-bit words are
// all zero. Detect once per thread from the first 4 entries (L1 broadcast).
// ---------------------------------------------------------------------------
__device__ __forceinline__ bool ei_is64(const int* __restrict__ ei) {
    return (ei[1] | ei[3] | ei[5] | ei[7]) == 0;
}
__device__ __forceinline__ int ei_load(const int* __restrict__ ei, long long pos, bool is64) {
    return is64 ? ei[pos * 2] : ei[pos];
}

// ---------------------------------------------------------------------------
// Fold the edge-feature path:  a_e1 = ea @ P1,  a_e2 = ea @ P2
//   P1 = We1 @ A1        (A1[k][h] = att_edge1[h][k-16h] on head-block diag)
//   P2 = We1 @ We2 @ A2
// ---------------------------------------------------------------------------
__global__ void precompute_kernel(const float* __restrict__ We1,
                                  const float* __restrict__ We2,
                                  const float* __restrict__ ate1,
                                  const float* __restrict__ ate2) {
    int j = threadIdx.x;  // 0..63
    __shared__ float A2p[64 * 4];
#pragma unroll
    for (int h = 0; h < 4; h++) {
        float s = 0.f;
#pragma unroll
        for (int c = 0; c < 16; c++) s += We2[j * 64 + h * 16 + c] * ate2[h * 16 + c];
        A2p[j * 4 + h] = s;
    }
    __syncthreads();
#pragma unroll
    for (int h = 0; h < 4; h++) {
        float s = 0.f;
#pragma unroll
        for (int c = 0; c < 16; c++) s += We1[j * 64 + h * 16 + c] * ate1[h * 16 + c];
        g_P[j * 8 + h] = s;
    }
#pragma unroll
    for (int h = 0; h < 4; h++) {
        float s = 0.f;
        for (int k = 0; k < 64; k++) s += We1[j * 64 + k] * A2p[k * 4 + h];
        g_P[j * 8 + 4 + h] = s;
    }
}

__global__ void zero_kernel() {
    int i = blockIdx.x * 256 + threadIdx.x;
    if (i < NN * 64) g_acc[i] = 0.f;
    if (i < NN * 4) g_denom[i] = 0.f;
}

// ---------------------------------------------------------------------------
// Node kernel: xp = relu?(input) @ W  [+ per-head att dot products]
// MODE 0: input = raw x rows (len IN)         -> g_xp, g_asrc, g_adst
// MODE 1: input = relu(g_acc / g_denom)       -> g_xp, g_asrc, g_adst
// MODE 2: input = relu(g_acc / g_denom), out = input @ W + bias -> outp
// 256 threads = 4 node-groups of 64; thread t owns output channel t.
// ---------------------------------------------------------------------------
template <int IN, int MODE>
__global__ void __launch_bounds__(256) node_kernel(const float* __restrict__ xin,
                                                   const float* __restrict__ W,
                                                   const float* __restrict__ attS,
                                                   const float* __restrict__ attD,
                                                   const float* __restrict__ bias,
                                                   float* __restrict__ outp) {
    __shared__ float Ws[IN * 64];
    __shared__ float xs[4][IN];
    __shared__ float aSs[64], aDs[64];
    for (int i = threadIdx.x; i < IN * 64; i += 256) Ws[i] = W[i];
    if (MODE < 2 && threadIdx.x < 64) {
        aSs[threadIdx.x] = attS[threadIdx.x];
        aDs[threadIdx.x] = attD[threadIdx.x];
    }
    int g = threadIdx.x >> 6, t = threadIdx.x & 63;
    int n = blockIdx.x * 4 + g;
    bool valid = n < NN;
    if (valid) {
        if (MODE == 0) {
            for (int k = t; k < IN; k += 64) xs[g][k] = xin[(size_t)n * IN + k];
        } else {
            float den = g_denom[n * 4 + (t >> 4)];
            float v = g_acc[n * 64 + t] / fmaxf(den, 1e-16f);
            xs[g][t] = fmaxf(v, 0.f);
        }
    }
    __syncthreads();
    if (!valid) return;
    float acc = 0.f;
#pragma unroll
    for (int k = 0; k < IN; k++) acc += xs[g][k] * Ws[k * 64 + t];
    if (MODE == 2) {
        outp[(size_t)n * 64 + t] = acc + bias[t];
    } else {
        g_xp[n * 64 + t] = acc;
        float r1 = acc * aSs[t];
        float r2 = acc * aDs[t];
#pragma unroll
        for (int o = 8; o; o >>= 1) {
            r1 += __shfl_xor_sync(0xffffffffu, r1, o);
            r2 += __shfl_xor_sync(0xffffffffu, r2, o);
        }
        if ((t & 15) == 0) {
            g_asrc[n * 4 + (t >> 4)] = r1;
            g_adst[n * 4 + (t >> 4)] = r2;
        }
    }
}

// ---------------------------------------------------------------------------
// Fused edge pass, layer 1. One warp per edge:
//  - stream edge_attr[e] (192 floats), reduce mean over 3 -> ea[64] (in smem)
//  - ea @ P gives a_e1[4] (used now) and a_e2[4] (stored for layer 2)
//  - w = exp(leakyrelu(asrc[src]+adst[dst]+a_e1)); scatter w*xp[src] via red.v4
// ---------------------------------------------------------------------------
__global__ void __launch_bounds__(256) edge_l1_kernel(const float* __restrict__ edge_attr,
                                                      const int* __restrict__ ei) {
    __shared__ float Ps[512];
    __shared__ float eas[8][64];
    for (int i = threadIdx.x; i < 512; i += 256) Ps[i] = g_P[i];
    __syncthreads();
    int wid = threadIdx.x >> 5, lane = threadIdx.x & 31;
    int e = blockIdx.x * 8 + wid;
    if (e >= EE) return;  // whole warp exits together

    const float* ea = edge_attr + (size_t)e * 192;
    float ea1 = (ea[lane] + ea[lane + 64] + ea[lane + 128]) * (1.f / 3.f);
    float ea2 = (ea[lane + 32] + ea[lane + 96] + ea[lane + 160]) * (1.f / 3.f);
    eas[wid][lane] = ea1;
    eas[wid][lane + 32] = ea2;
    __syncwarp();

    // lane -> (h = lane>>2 in 0..7, 16-wide j chunk (lane&3)); 2-shfl reduce
    int h4 = lane >> 2;
    int j0 = (lane & 3) * 16;
    float p = 0.f;
#pragma unroll
    for (int i = 0; i < 16; i++) p += eas[wid][j0 + i] * Ps[(j0 + i) * 8 + h4];
    p += __shfl_xor_sync(0xffffffffu, p, 1);
    p += __shfl_xor_sync(0xffffffffu, p, 2);

    bool is64 = ei_is64(ei);
    int s = ei_load(ei, e, is64);
    int d = ei_load(ei, (long long)EE + e, is64);
    if (lane >= 16) {
        if ((lane & 3) == 0) g_ae2[(size_t)e * 4 + (h4 - 4)] = p;  // layer-2 term
    } else {
        float a = g_asrc[s * 4 + h4] + g_adst[d * 4 + h4] + p;
        a = a > 0.f ? a : 0.2f * a;
        float w = __expf(a);
        float4 v = reinterpret_cast<const float4*>(g_xp)[s * 16 + lane];
        atomicAdd(reinterpret_cast<float4*>(g_acc) + (d * 16 + lane),
                  make_float4(w * v.x, w * v.y, w * v.z, w * v.w));
        if ((lane & 3) == 0) atomicAdd(&g_denom[d * 4 + h4], w);
    }
}

// ---------------------------------------------------------------------------
// Edge pass, layer 2. 16 threads per edge (a_e2 precomputed, no edge_attr read)
// ---------------------------------------------------------------------------
__global__ void __launch_bounds__(256) edge_l2_kernel(const int* __restrict__ ei) {
    int e = blockIdx.x * 16 + (threadIdx.x >> 4);
    int l = threadIdx.x & 15;
    if (e >= EE) return;
    bool is64 = ei_is64(ei);
    int s = ei_load(ei, e, is64);
    int d = ei_load(ei, (long long)EE + e, is64);
    int h = l >> 2;
    float a = g_asrc[s * 4 + h] + g_adst[d * 4 + h] + g_ae2[(size_t)e * 4 + h];
    a = a > 0.f ? a : 0.2f * a;
    float w = __expf(a);
    float4 v = reinterpret_cast<const float4*>(g_xp)[s * 16 + l];
    atomicAdd(reinterpret_cast<float4*>(g_acc) + (d * 16 + l),
              make_float4(w * v.x, w * v.y, w * v.z, w * v.w));
    if (!(l & 3)) atomicAdd(&g_denom[d * 4 + h], w);
}

// ---------------------------------------------------------------------------
extern "C" void kernel_launch(void* const* d_in, const int* in_sizes, int n_in,
                              void* d_out, int out_size) {
    const float* x = (const float*)d_in[0];
    const int* ei = (const int*)d_in[1];
    const float* edge_attr = (const float*)d_in[2];
    const float* W1 = (const float*)d_in[3];
    const float* We1 = (const float*)d_in[4];
    const float* as1 = (const float*)d_in[5];
    const float* ad1 = (const float*)d_in[6];
    const float* ae1 = (const float*)d_in[7];
    const float* W2 = (const float*)d_in[8];
    const float* We2 = (const float*)d_in[9];
    const float* as2 = (const float*)d_in[10];
    const float* ad2 = (const float*)d_in[11];
    const float* ae2 = (const float*)d_in[12];
    const float* Wout = (const float*)d_in[13];
    const float* bout = (const float*)d_in[14];
    float* out = (float*)d_out;

    precompute_kernel<<<1, 64>>>(We1, We2, ae1, ae2);
    node_kernel<128, 0><<<(NN + 3) / 4, 256>>>(x, W1, as1, ad1, nullptr, nullptr);
    zero_kernel<<<(NN * 64 + 255) / 256, 256>>>();
    edge_l1_kernel<<<(EE + 7) / 8, 256>>>(edge_attr, ei);
    node_kernel<64, 1><<<(NN + 3) / 4, 256>>>(nullptr, W2, as2, ad2, nullptr, nullptr);
    zero_kernel<<<(NN * 64 + 255) / 256, 256>>>();
    edge_l2_kernel<<<(EE + 15) / 16, 256>>>(ei);
    node_kernel<64, 2><<<(NN + 3) / 4, 256>>>(nullptr, Wout, nullptr, nullptr, bout, out);
}

// round 6
// speedup vs baseline: 1.4572x; 1.4572x over previous
#include <cuda_runtime.h>

#define NN 100000
#define EE 1600000
#define NBLK1 391   // ceil(NN/256)

// ---------------- scratch (device globals; no allocation allowed) ----------
__device__ __align__(16) float g_ae[EE * 8];     // per-edge logit terms: h0-3 L1, h4-7 L2 (51.2MB)
__device__ __align__(16) float g_xp[NN * 64];    // projected node feats (25.6MB)
__device__ __align__(16) float g_acc[NN * 64];   // normalized aggregation (25.6MB)
__device__ __align__(16) int2  g_el[EE];         // CSR edge list: (src, edge_id) (12.8MB)
__device__ float g_asrc[NN * 4];
__device__ float g_adst[NN * 4];
__device__ int   g_cnt[NN];
__device__ int   g_off[NN];
__device__ int   g_cur[NN];      // fill cursor; after fill = segment end
__device__ int   g_part[512];
__device__ int   g_part2[512];
__device__ float g_P[512];       // folded [64 j][8 h]

// ---------------------------------------------------------------------------
// edge_index dtype hedge (int64 vs int32): int64 little-endian has zero odd words.
// ---------------------------------------------------------------------------
__device__ __forceinline__ bool ei_is64(const int* __restrict__ ei) {
    return (ei[1] | ei[3] | ei[5] | ei[7]) == 0;
}
__device__ __forceinline__ int ei_load(const int* __restrict__ ei, long long pos, bool is64) {
    return is64 ? ei[pos * 2] : ei[pos];
}

// ---------------------------------------------------------------------------
// Fold edge-feature path: P[:,0:4] = We1@A1 (layer1), P[:,4:8] = We1@We2@A2 (layer2)
// ---------------------------------------------------------------------------
__global__ void precompute_kernel(const float* __restrict__ We1,
                                  const float* __restrict__ We2,
                                  const float* __restrict__ ate1,
                                  const float* __restrict__ ate2) {
    int j = threadIdx.x;  // 0..63
    __shared__ float A2p[64 * 4];
#pragma unroll
    for (int h = 0; h < 4; h++) {
        float s = 0.f;
#pragma unroll
        for (int c = 0; c < 16; c++) s += We2[j * 64 + h * 16 + c] * ate2[h * 16 + c];
        A2p[j * 4 + h] = s;
    }
    __syncthreads();
#pragma unroll
    for (int h = 0; h < 4; h++) {
        float s = 0.f;
#pragma unroll
        for (int c = 0; c < 16; c++) s += We1[j * 64 + h * 16 + c] * ate1[h * 16 + c];
        g_P[j * 8 + h] = s;
    }
#pragma unroll
    for (int h = 0; h < 4; h++) {
        float s = 0.f;
        for (int k = 0; k < 64; k++) s += We1[j * 64 + k] * A2p[k * 4 + h];
        g_P[j * 8 + 4 + h] = s;
    }
}

// ---------------------------------------------------------------------------
// ae kernel: stream edge_attr once; ea = mean over 3 slices; g_ae = ea @ P.
// 32 edges/block, conflict-free tiled smem GEMM (pads of 68 keep float4 align
// AND distinct banks). Thread (e = t>>3, h = t&7) computes one output.
// ---------------------------------------------------------------------------
__global__ void __launch_bounds__(256) ae_kernel(const float* __restrict__ edge_attr) {
    __shared__ float sEas[32 * 68];   // 8.7KB, row stride 272B (16B-aligned)
    __shared__ float sPt[8 * 68];     // transposed P: [h][j]
    const float4* __restrict__ ea4 = (const float4*)edge_attr;
    long long e0 = (long long)blockIdx.x * 32;
    int t = threadIdx.x;

    // stage transposed P
#pragma unroll
    for (int i = 0; i < 2; i++) {
        int idx = t + i * 256;
        sPt[(idx & 7) * 68 + (idx >> 3)] = g_P[idx];
    }
    // stage mean-reduced edge features: 32 edges x 16 float4
#pragma unroll
    for (int i = 0; i < 2; i++) {
        int idx = t + i * 256;           // 0..511
        int e = idx >> 4, j4 = idx & 15;
        long long base = (e0 + e) * 48;
        float4 a = ea4[base + j4];
        float4 b = ea4[base + 16 + j4];
        float4 c = ea4[base + 32 + j4];
        float4 m = make_float4((a.x + b.x + c.x) * (1.f / 3.f),
                               (a.y + b.y + c.y) * (1.f / 3.f),
                               (a.z + b.z + c.z) * (1.f / 3.f),
                               (a.w + b.w + c.w) * (1.f / 3.f));
        *(float4*)&sEas[e * 68 + j4 * 4] = m;
    }
    __syncthreads();

    int e = t >> 3, h = t & 7;
    const float* er = &sEas[e * 68];
    const float* pr = &sPt[h * 68];
    float acc = 0.f;
#pragma unroll
    for (int j4 = 0; j4 < 16; j4++) {
        float4 u = *(const float4*)&er[j4 * 4];
        float4 p = *(const float4*)&pr[j4 * 4];
        acc += u.x * p.x + u.y * p.y + u.z * p.z + u.w * p.w;
    }
    g_ae[(e0 + e) * 8 + h] = acc;   // coalesced: 256 consecutive floats
}

// ---------------------------------------------------------------------------
// CSR build: histogram -> 2-level exclusive scan -> fill
// ---------------------------------------------------------------------------
__global__ void zero_cnt_kernel() {
    int i = blockIdx.x * 256 + threadIdx.x;
    if (i < NN) g_cnt[i] = 0;
}
__global__ void hist_kernel(const int* __restrict__ ei) {
    int e = blockIdx.x * 256 + threadIdx.x;
    bool is64 = ei_is64(ei);
    int d = ei_load(ei, (long long)EE + e, is64);
    atomicAdd(&g_cnt[d], 1);
}
__global__ void scan1_kernel() {
    __shared__ int s[256];
    int i = blockIdx.x * 256 + threadIdx.x;
    int c = (i < NN) ? g_cnt[i] : 0;
    s[threadIdx.x] = c;
    __syncthreads();
#pragma unroll
    for (int o = 1; o < 256; o <<= 1) {
        int v = (threadIdx.x >= o) ? s[threadIdx.x - o] : 0;
        __syncthreads();
        s[threadIdx.x] += v;
        __syncthreads();
    }
    int incl = s[threadIdx.x];
    if (i < NN) g_off[i] = incl - c;       // local exclusive
    if (threadIdx.x == 255) g_part[blockIdx.x] = incl;
}
__global__ void scan2_kernel() {
    __shared__ int s[512];
    int t = threadIdx.x;
    int v = (t < NBLK1) ? g_part[t] : 0;
    s[t] = v;
    __syncthreads();
#pragma unroll
    for (int o = 1; o < 512; o <<= 1) {
        int u = (t >= o) ? s[t - o] : 0;
        __syncthreads();
        s[t] += u;
        __syncthreads();
    }
    g_part2[t] = s[t] - v;                 // exclusive
}
__global__ void scan3_kernel() {
    int i = blockIdx.x * 256 + threadIdx.x;
    if (i < NN) {
        int o = g_off[i] + g_part2[i >> 8];
        g_off[i] = o;
        g_cur[i] = o;
    }
}
__global__ void fill_kernel(const int* __restrict__ ei) {
    int e = blockIdx.x * 256 + threadIdx.x;
    bool is64 = ei_is64(ei);
    int s = ei_load(ei, e, is64);
    int d = ei_load(ei, (long long)EE + e, is64);
    int pos = atomicAdd(&g_cur[d], 1);
    g_el[pos] = make_int2(s, e);
}

// ---------------------------------------------------------------------------
// Gather aggregation (per layer). One warp per node; lane owns channels 2l,2l+1.
// Every lane computes the softmax weight for ITS head (l>>3) -> no shuffles,
// no atomics. Writes normalized aggregate to g_acc.
// ---------------------------------------------------------------------------
template <int LAYER>
__global__ void __launch_bounds__(256) gather_kernel() {
    int lane = threadIdx.x & 31;
    int n = blockIdx.x * 8 + (threadIdx.x >> 5);
    int h = lane >> 3;
    const float2* __restrict__ xp2 = (const float2*)g_xp;
    float aD = g_adst[n * 4 + h];
    int p = g_off[n], pend = g_cur[n];
    float2 acc = make_float2(0.f, 0.f);
    float den = 0.f;
    for (; p < pend; p++) {
        int2 se = g_el[p];
        float a = g_asrc[se.x * 4 + h] + aD + g_ae[(size_t)se.y * 8 + LAYER * 4 + h];
        a = a > 0.f ? a : 0.2f * a;
        float w = __expf(a);
        float2 v = xp2[se.x * 32 + lane];
        acc.x += w * v.x;
        acc.y += w * v.y;
        den += w;
    }
    float inv = 1.f / fmaxf(den, 1e-16f);
    ((float2*)g_acc)[n * 32 + lane] = make_float2(acc.x * inv, acc.y * inv);
}

// ---------------------------------------------------------------------------
// Node kernel: xp = relu?(input) @ W  [+ per-head att dot products]
// MODE 0: input = raw x rows (len IN)   -> g_xp, g_asrc, g_adst
// MODE 1: input = relu(g_acc)           -> g_xp, g_asrc, g_adst
// MODE 2: input = relu(g_acc), out = input @ W + bias -> outp
// ---------------------------------------------------------------------------
template <int IN, int MODE>
__global__ void __launch_bounds__(256) node_kernel(const float* __restrict__ xin,
                                                   const float* __restrict__ W,
                                                   const float* __restrict__ attS,
                                                   const float* __restrict__ attD,
                                                   const float* __restrict__ bias,
                                                   float* __restrict__ outp) {
    __shared__ float Ws[IN * 64];
    __shared__ float xs[4][IN];
    __shared__ float aSs[64], aDs[64];
    for (int i = threadIdx.x; i < IN * 64; i += 256) Ws[i] = W[i];
    if (MODE < 2 && threadIdx.x < 64) {
        aSs[threadIdx.x] = attS[threadIdx.x];
        aDs[threadIdx.x] = attD[threadIdx.x];
    }
    int g = threadIdx.x >> 6, t = threadIdx.x & 63;
    int n = blockIdx.x * 4 + g;
    if (MODE == 0) {
        for (int k = t; k < IN; k += 64) xs[g][k] = xin[(size_t)n * IN + k];
    } else {
        xs[g][t] = fmaxf(g_acc[n * 64 + t], 0.f);
    }
    __syncthreads();
    float acc = 0.f;
#pragma unroll
    for (int k = 0; k < IN; k++) acc += xs[g][k] * Ws[k * 64 + t];
    if (MODE == 2) {
        outp[(size_t)n * 64 + t] = acc + bias[t];
    } else {
        g_xp[n * 64 + t] = acc;
        float r1 = acc * aSs[t];
        float r2 = acc * aDs[t];
#pragma unroll
        for (int o = 8; o; o >>= 1) {
            r1 += __shfl_xor_sync(0xffffffffu, r1, o);
            r2 += __shfl_xor_sync(0xffffffffu, r2, o);
        }
        if ((t & 15) == 0) {
            g_asrc[n * 4 + (t >> 4)] = r1;
            g_adst[n * 4 + (t >> 4)] = r2;
        }
    }
}

// ---------------------------------------------------------------------------
extern "C" void kernel_launch(void* const* d_in, const int* in_sizes, int n_in,
                              void* d_out, int out_size) {
    const float* x = (const float*)d_in[0];
    const int* ei = (const int*)d_in[1];
    const float* edge_attr = (const float*)d_in[2];
    const float* W1 = (const float*)d_in[3];
    const float* We1 = (const float*)d_in[4];
    const float* as1 = (const float*)d_in[5];
    const float* ad1 = (const float*)d_in[6];
    const float* ae1 = (const float*)d_in[7];
    const float* W2 = (const float*)d_in[8];
    const float* We2 = (const float*)d_in[9];
    const float* as2 = (const float*)d_in[10];
    const float* ad2 = (const float*)d_in[11];
    const float* ae2 = (const float*)d_in[12];
    const float* Wout = (const float*)d_in[13];
    const float* bout = (const float*)d_in[14];
    float* out = (float*)d_out;

    // CSR build (graph is shared by both layers; built fresh every launch)
    zero_cnt_kernel<<<NBLK1, 256>>>();
    hist_kernel<<<EE / 256, 256>>>(ei);
    scan1_kernel<<<NBLK1, 256>>>();
    scan2_kernel<<<1, 512>>>();
    scan3_kernel<<<NBLK1, 256>>>();
    fill_kernel<<<EE / 256, 256>>>(ei);

    precompute_kernel<<<1, 64>>>(We1, We2, ae1, ae2);
    ae_kernel<<<EE / 32, 256>>>(edge_attr);

    node_kernel<128, 0><<<NN / 4, 256>>>(x, W1, as1, ad1, nullptr, nullptr);
    gather_kernel<0><<<NN / 8, 256>>>();
    node_kernel<64, 1><<<NN / 4, 256>>>(nullptr, W2, as2, ad2, nullptr, nullptr);
    gather_kernel<1><<<NN / 8, 256>>>();
    node_kernel<64, 2><<<NN / 4, 256>>>(nullptr, Wout, nullptr, nullptr, bout, out);
}

// round 8
// speedup vs baseline: 1.9264x; 1.3220x over previous
#include <cuda_runtime.h>

#define NN 100000
#define EE 1600000
#define NBLK1 391   // ceil(NN/256)

// ---------------- scratch (device globals; no allocation allowed) ----------
__device__ __align__(16) float g_ae[EE * 8];     // CSR-ordered logit terms: h0-3 L1, h4-7 L2
__device__ __align__(16) float g_xp[NN * 64];    // projected node feats (25.6MB)
__device__ __align__(16) float g_acc[NN * 64];   // normalized aggregation (25.6MB)
__device__ int   g_el[EE];                        // CSR edge list: src node (6.4MB)
__device__ int   g_pos[EE];                       // edge id -> CSR slot (6.4MB)
__device__ float g_asrc[NN * 4];
__device__ float g_adst[NN * 4];
__device__ int   g_cnt[NN];
__device__ int   g_off[NN];
__device__ int   g_cur[NN];      // fill cursor; after fill = segment end
__device__ int   g_part[512];
__device__ int   g_part2[512];
__device__ float g_P[512];       // folded [64 j][8 h]
__device__ float g_W1t[64 * 128];   // transposed weights [c][k]
__device__ float g_W2t[64 * 64];
__device__ float g_Wot[64 * 64];

// ---------------------------------------------------------------------------
// edge_index dtype hedge (int64 vs int32): int64 little-endian has zero odd words.
// ---------------------------------------------------------------------------
__device__ __forceinline__ bool ei_is64(const int* __restrict__ ei) {
    return (ei[1] | ei[3] | ei[5] | ei[7]) == 0;
}
__device__ __forceinline__ int ei_load(const int* __restrict__ ei, long long pos, bool is64) {
    return is64 ? ei[pos * 2] : ei[pos];
}

// ---------------------------------------------------------------------------
// Fold edge-feature path: P[:,0:4] = We1@A1 (layer1), P[:,4:8] = We1@We2@A2 (layer2)
// ---------------------------------------------------------------------------
__global__ void precompute_kernel(const float* __restrict__ We1,
                                  const float* __restrict__ We2,
                                  const float* __restrict__ ate1,
                                  const float* __restrict__ ate2) {
    int j = threadIdx.x;  // 0..63
    __shared__ float A2p[64 * 4];
#pragma unroll
    for (int h = 0; h < 4; h++) {
        float s = 0.f;
#pragma unroll
        for (int c = 0; c < 16; c++) s += We2[j * 64 + h * 16 + c] * ate2[h * 16 + c];
        A2p[j * 4 + h] = s;
    }
    __syncthreads();
#pragma unroll
    for (int h = 0; h < 4; h++) {
        float s = 0.f;
#pragma unroll
        for (int c = 0; c < 16; c++) s += We1[j * 64 + h * 16 + c] * ate1[h * 16 + c];
        g_P[j * 8 + h] = s;
    }
#pragma unroll
    for (int h = 0; h < 4; h++) {
        float s = 0.f;
        for (int k = 0; k < 64; k++) s += We1[j * 64 + k] * A2p[k * 4 + h];
        g_P[j * 8 + 4 + h] = s;
    }
}

// one-time weight transpose: g_W*t[c*IN + k] = W[k*64 + c]
__global__ void transpose_kernel(const float* __restrict__ W1,
                                 const float* __restrict__ W2,
                                 const float* __restrict__ Wo) {
    int t = blockIdx.x * 256 + threadIdx.x;
    if (t < 8192) { int k = t >> 6, c = t & 63; g_W1t[c * 128 + k] = W1[t]; }
    if (t < 4096) {
        int k = t >> 6, c = t & 63;
        g_W2t[c * 64 + k] = W2[t];
        g_Wot[c * 64 + k] = Wo[t];
    }
}

// ---------------------------------------------------------------------------
// ae kernel: stream edge_attr once; ea = mean over 3 slices; logits = ea @ P,
// stored at the edge's CSR slot so gather passes read g_ae sequentially.
// ---------------------------------------------------------------------------
__global__ void __launch_bounds__(256) ae_kernel(const float* __restrict__ edge_attr) {
    __shared__ float sEas[32 * 68];
    __shared__ float sPt[8 * 68];     // transposed P: [h][j]
    __shared__ int sPos[32];
    const float4* __restrict__ ea4 = (const float4*)edge_attr;
    long long e0 = (long long)blockIdx.x * 32;
    int t = threadIdx.x;

#pragma unroll
    for (int i = 0; i < 2; i++) {
        int idx = t + i * 256;
        sPt[(idx & 7) * 68 + (idx >> 3)] = g_P[idx];
    }
    if (t < 32) sPos[t] = g_pos[e0 + t];
#pragma unroll
    for (int i = 0; i < 2; i++) {
        int idx = t + i * 256;           // 0..511
        int e = idx >> 4, j4 = idx & 15;
        long long base = (e0 + e) * 48;
        float4 a = ea4[base + j4];
        float4 b = ea4[base + 16 + j4];
        float4 c = ea4[base + 32 + j4];
        float4 m = make_float4((a.x + b.x + c.x) * (1.f / 3.f),
                               (a.y + b.y + c.y) * (1.f / 3.f),
                               (a.z + b.z + c.z) * (1.f / 3.f),
                               (a.w + b.w + c.w) * (1.f / 3.f));
        *(float4*)&sEas[e * 68 + j4 * 4] = m;
    }
    __syncthreads();

    int e = t >> 3, h = t & 7;
    const float* er = &sEas[e * 68];
    const float* pr = &sPt[h * 68];
    float acc = 0.f;
#pragma unroll
    for (int j4 = 0; j4 < 16; j4++) {
        float4 u = *(const float4*)&er[j4 * 4];
        float4 p = *(const float4*)&pr[j4 * 4];
        acc += u.x * p.x + u.y * p.y + u.z * p.z + u.w * p.w;
    }
    g_ae[(size_t)sPos[e] * 8 + h] = acc;   // 32B-sector write per edge
}

// ---------------------------------------------------------------------------
// CSR build: histogram -> 2-level exclusive scan -> fill (records slot per edge)
// ---------------------------------------------------------------------------
__global__ void zero_cnt_kernel() {
    int i = blockIdx.x * 256 + threadIdx.x;
    if (i < NN) g_cnt[i] = 0;
}
__global__ void hist_kernel(const int* __restrict__ ei) {
    int e = blockIdx.x * 256 + threadIdx.x;
    bool is64 = ei_is64(ei);
    int d = ei_load(ei, (long long)EE + e, is64);
    atomicAdd(&g_cnt[d], 1);
}
__global__ void scan1_kernel() {
    __shared__ int s[256];
    int i = blockIdx.x * 256 + threadIdx.x;
    int c = (i < NN) ? g_cnt[i] : 0;
    s[threadIdx.x] = c;
    __syncthreads();
#pragma unroll
    for (int o = 1; o < 256; o <<= 1) {
        int v = (threadIdx.x >= o) ? s[threadIdx.x - o] : 0;
        __syncthreads();
        s[threadIdx.x] += v;
        __syncthreads();
    }
    int incl = s[threadIdx.x];
    if (i < NN) g_off[i] = incl - c;
    if (threadIdx.x == 255) g_part[blockIdx.x] = incl;
}
__global__ void scan2_kernel() {
    __shared__ int s[512];
    int t = threadIdx.x;
    int v = (t < NBLK1) ? g_part[t] : 0;
    s[t] = v;
    __syncthreads();
#pragma unroll
    for (int o = 1; o < 512; o <<= 1) {
        int u = (t >= o) ? s[t - o] : 0;
        __syncthreads();
        s[t] += u;
        __syncthreads();
    }
    g_part2[t] = s[t] - v;
}
__global__ void scan3_kernel() {
    int i = blockIdx.x * 256 + threadIdx.x;
    if (i < NN) {
        int o = g_off[i] + g_part2[i >> 8];
        g_off[i] = o;
        g_cur[i] = o;
    }
}
__global__ void fill_kernel(const int* __restrict__ ei) {
    int e = blockIdx.x * 256 + threadIdx.x;
    bool is64 = ei_is64(ei);
    int s = ei_load(ei, e, is64);
    int d = ei_load(ei, (long long)EE + e, is64);
    int pos = atomicAdd(&g_cur[d], 1);
    g_el[pos] = s;
    g_pos[e] = pos;
}

// ---------------------------------------------------------------------------
// Gather aggregation (per layer). One warp per node; lane owns channels 2l,2l+1;
// every lane computes the softmax weight for ITS head -> no shuffles/atomics.
// g_ae reads are sequential (CSR-ordered). Writes normalized aggregate.
// ---------------------------------------------------------------------------
template <int LAYER>
__global__ void __launch_bounds__(256) gather_kernel() {
    int lane = threadIdx.x & 31;
    int n = blockIdx.x * 8 + (threadIdx.x >> 5);
    int h = lane >> 3;
    const float2* __restrict__ xp2 = (const float2*)g_xp;
    float aD = g_adst[n * 4 + h];
    int p = g_off[n], pend = g_cur[n];
    float2 acc = make_float2(0.f, 0.f);
    float den = 0.f;
#pragma unroll 4
    for (; p < pend; p++) {
        int s = g_el[p];
        float a = g_asrc[s * 4 + h] + aD + g_ae[(size_t)p * 8 + LAYER * 4 + h];
        a = a > 0.f ? a : 0.2f * a;
        float w = __expf(a);
        float2 v = xp2[s * 32 + lane];
        acc.x += w * v.x;
        acc.y += w * v.y;
        den += w;
    }
    float inv = 1.f / fmaxf(den, 1e-16f);
    ((float2*)g_acc)[n * 32 + lane] = make_float2(acc.x * inv, acc.y * inv);
}

// ---------------------------------------------------------------------------
// Node GEMM, register-blocked + float4 smem. 16 nodes/block, 256 threads.
// Thread owns channel c = t&63 for the 4 nodes of group q = t>>6.
// Weight array selected by WSEL *inside device code* (0=W1t,1=W2t,2=Wot) —
// device globals must never be passed as kernel arguments from host.
// MODE 0: in = x rows (len IN)  -> g_xp + att dots
// MODE 1: in = relu(g_acc)      -> g_xp + att dots
// MODE 2: in = relu(g_acc), out = in @ W + bias
// ---------------------------------------------------------------------------
template <int IN, int MODE, int WSEL>
__global__ void __launch_bounds__(256) node_kernel(const float* __restrict__ xin,
                                                   const float* __restrict__ attS,
                                                   const float* __restrict__ attD,
                                                   const float* __restrict__ bias,
                                                   float* __restrict__ outp) {
    const float* __restrict__ Wt = (WSEL == 0) ? g_W1t : (WSEL == 1) ? g_W2t : g_Wot;
    const int INp = IN + 4;
    __shared__ float Wts[64 * INp];
    __shared__ float xs[16 * INp];
    __shared__ float aSs[64], aDs[64];
    int t = threadIdx.x;
    for (int i = t; i < 64 * IN; i += 256) Wts[(i / IN) * INp + (i % IN)] = Wt[i];
    if (MODE < 2 && t < 64) { aSs[t] = attS[t]; aDs[t] = attD[t]; }
    int nb0 = blockIdx.x * 16;
    if (MODE == 0) {
        for (int i = t; i < 16 * IN; i += 256)
            xs[(i / IN) * INp + (i % IN)] = xin[(size_t)nb0 * IN + i];
    } else {
        for (int i = t; i < 16 * 64; i += 256)
            xs[(i >> 6) * INp + (i & 63)] = fmaxf(g_acc[(size_t)nb0 * 64 + i], 0.f);
    }
    __syncthreads();

    int c = t & 63, q = t >> 6;
    const float* wr = &Wts[c * INp];
    const float* x0 = &xs[(q * 4 + 0) * INp];
    const float* x1 = &xs[(q * 4 + 1) * INp];
    const float* x2 = &xs[(q * 4 + 2) * INp];
    const float* x3 = &xs[(q * 4 + 3) * INp];
    float a0 = 0.f, a1 = 0.f, a2 = 0.f, a3 = 0.f;
#pragma unroll
    for (int k = 0; k < IN; k += 4) {
        float4 w = *(const float4*)&wr[k];
        float4 u0 = *(const float4*)&x0[k];
        float4 u1 = *(const float4*)&x1[k];
        float4 u2 = *(const float4*)&x2[k];
        float4 u3 = *(const float4*)&x3[k];
        a0 += w.x * u0.x + w.y * u0.y + w.z * u0.z + w.w * u0.w;
        a1 += w.x * u1.x + w.y * u1.y + w.z * u1.z + w.w * u1.w;
        a2 += w.x * u2.x + w.y * u2.y + w.z * u2.z + w.w * u2.w;
        a3 += w.x * u3.x + w.y * u3.y + w.z * u3.z + w.w * u3.w;
    }
    int nb = nb0 + q * 4;
    if (MODE == 2) {
        float b = bias[c];
        outp[(size_t)(nb + 0) * 64 + c] = a0 + b;
        outp[(size_t)(nb + 1) * 64 + c] = a1 + b;
        outp[(size_t)(nb + 2) * 64 + c] = a2 + b;
        outp[(size_t)(nb + 3) * 64 + c] = a3 + b;
    } else {
        float aS = aSs[c], aD = aDs[c];
        int lane = t & 31, head = c >> 4;
        float av[4] = {a0, a1, a2, a3};
#pragma unroll
        for (int j = 0; j < 4; j++) {
            g_xp[(size_t)(nb + j) * 64 + c] = av[j];
            float r1 = av[j] * aS;
            float r2 = av[j] * aD;
#pragma unroll
            for (int o = 8; o; o >>= 1) {
                r1 += __shfl_xor_sync(0xffffffffu, r1, o);
                r2 += __shfl_xor_sync(0xffffffffu, r2, o);
            }
            if ((lane & 15) == 0) {
                g_asrc[(nb + j) * 4 + head] = r1;
                g_adst[(nb + j) * 4 + head] = r2;
            }
        }
    }
}

// ---------------------------------------------------------------------------
extern "C" void kernel_launch(void* const* d_in, const int* in_sizes, int n_in,
                              void* d_out, int out_size) {
    const float* x = (const float*)d_in[0];
    const int* ei = (const int*)d_in[1];
    const float* edge_attr = (const float*)d_in[2];
    const float* W1 = (const float*)d_in[3];
    const float* We1 = (const float*)d_in[4];
    const float* as1 = (const float*)d_in[5];
    const float* ad1 = (const float*)d_in[6];
    const float* ae1 = (const float*)d_in[7];
    const float* W2 = (const float*)d_in[8];
    const float* We2 = (const float*)d_in[9];
    const float* as2 = (const float*)d_in[10];
    const float* ad2 = (const float*)d_in[11];
    const float* ae2 = (const float*)d_in[12];
    const float* Wout = (const float*)d_in[13];
    const float* bout = (const float*)d_in[14];
    float* out = (float*)d_out;

    // CSR build
    zero_cnt_kernel<<<NBLK1, 256>>>();
    hist_kernel<<<EE / 256, 256>>>(ei);
    scan1_kernel<<<NBLK1, 256>>>();
    scan2_kernel<<<1, 512>>>();
    scan3_kernel<<<NBLK1, 256>>>();
    fill_kernel<<<EE / 256, 256>>>(ei);

    precompute_kernel<<<1, 64>>>(We1, We2, ae1, ae2);
    transpose_kernel<<<32, 256>>>(W1, W2, Wout);
    ae_kernel<<<EE / 32, 256>>>(edge_attr);

    node_kernel<128, 0, 0><<<NN / 16, 256>>>(x, as1, ad1, nullptr, nullptr);
    gather_kernel<0><<<NN / 8, 256>>>();
    node_kernel<64, 1, 1><<<NN / 16, 256>>>(nullptr, as2, ad2, nullptr, nullptr);
    gather_kernel<1><<<NN / 8, 256>>>();
    node_kernel<64, 2, 2><<<NN / 16, 256>>>(nullptr, nullptr, nullptr, bout, out);
}

// round 10
// speedup vs baseline: 2.0377x; 1.0578x over previous
#include <cuda_runtime.h>

#define NN 100000
#define EE 1600000
#define NBLK1 391   // ceil(NN/256)
#define AE_BLOCKS (EE / 32)      // 50000
#define N0_BLOCKS (NN / 16)      // 6250

typedef unsigned long long u64;

// ---------------- scratch (device globals; no allocation allowed) ----------
__device__ __align__(16) float g_ae[EE * 8];     // EDGE-ordered logit terms: h0-3 L1, h4-7 L2
__device__ __align__(16) float g_xp[NN * 64];    // projected node feats (25.6MB)
__device__ __align__(16) float g_acc[NN * 64];   // normalized aggregation (25.6MB)
__device__ __align__(16) int2  g_el2[EE];        // CSR: (src, edge_id) per slot (12.8MB)
__device__ float g_asrc[NN * 4];
__device__ float g_adst[NN * 4];
__device__ int   g_cnt[NN];
__device__ int   g_off[NN];
__device__ int   g_cur[NN];      // fill cursor; after fill = segment end
__device__ int   g_part[512];
__device__ int   g_part2[512];
__device__ float g_P[512];       // folded [64 j][8 h]
__device__ float g_W1t[64 * 128];   // transposed weights [c][k]
__device__ float g_W2t[64 * 64];
__device__ float g_Wot[64 * 64];

// ---------------------------------------------------------------------------
// Packed f32x2 FMA (Blackwell) + horizontal sum
// ---------------------------------------------------------------------------
__device__ __forceinline__ u64 ffma2(u64 a, u64 b, u64 c) {
    u64 d;
    asm("fma.rn.f32x2 %0, %1, %2, %3;" : "=l"(d) : "l"(a), "l"(b), "l"(c));
    return d;
}
__device__ __forceinline__ float hsum2(u64 p) {
    return __uint_as_float((unsigned)p) + __uint_as_float((unsigned)(p >> 32));
}

// ---------------------------------------------------------------------------
// edge_index dtype hedge (int64 vs int32): int64 little-endian has zero odd words.
// ---------------------------------------------------------------------------
__device__ __forceinline__ bool ei_is64(const int* __restrict__ ei) {
    return (ei[1] | ei[3] | ei[5] | ei[7]) == 0;
}
__device__ __forceinline__ int ei_load(const int* __restrict__ ei, long long pos, bool is64) {
    return is64 ? ei[pos * 2] : ei[pos];
}

// ---------------------------------------------------------------------------
// setup kernel: blocks 0..390 zero g_cnt; block 391 folds P; blocks 392..423
// transpose the three weight matrices.
// ---------------------------------------------------------------------------
__global__ void __launch_bounds__(256) setup_kernel(const float* __restrict__ We1,
                                                    const float* __restrict__ We2,
                                                    const float* __restrict__ ate1,
                                                    const float* __restrict__ ate2,
                                                    const float* __restrict__ W1,
                                                    const float* __restrict__ W2,
                                                    const float* __restrict__ Wo) {
    int b = blockIdx.x, t = threadIdx.x;
    if (b < NBLK1) {
        int i = b * 256 + t;
        if (i < NN) g_cnt[i] = 0;
    } else if (b == NBLK1) {
        // fold edge-feature path: P[:,0:4]=We1@A1, P[:,4:8]=We1@We2@A2
        __shared__ float A2p[64 * 4];
        int j = t;
        if (j < 64) {
#pragma unroll
            for (int h = 0; h < 4; h++) {
                float s = 0.f;
#pragma unroll
                for (int c = 0; c < 16; c++) s += We2[j * 64 + h * 16 + c] * ate2[h * 16 + c];
                A2p[j * 4 + h] = s;
            }
        }
        __syncthreads();
        if (j < 64) {
#pragma unroll
            for (int h = 0; h < 4; h++) {
                float s = 0.f;
#pragma unroll
                for (int c = 0; c < 16; c++) s += We1[j * 64 + h * 16 + c] * ate1[h * 16 + c];
                g_P[j * 8 + h] = s;
            }
#pragma unroll
            for (int h = 0; h < 4; h++) {
                float s = 0.f;
                for (int k = 0; k < 64; k++) s += We1[j * 64 + k] * A2p[k * 4 + h];
                g_P[j * 8 + 4 + h] = s;
            }
        }
    } else {
        int i = (b - NBLK1 - 1) * 256 + t;   // 0..8191
        int k = i >> 6, c = i & 63;
        g_W1t[c * 128 + k] = W1[i];
        if (i < 4096) {
            g_W2t[c * 64 + k] = W2[i];
            g_Wot[c * 64 + k] = Wo[i];
        }
    }
}

// ---------------------------------------------------------------------------
// CSR build: histogram -> 2-level exclusive scan -> fill (int2 src,edge_id)
// ---------------------------------------------------------------------------
__global__ void hist_kernel(const int* __restrict__ ei) {
    int e = blockIdx.x * 256 + threadIdx.x;
    bool is64 = ei_is64(ei);
    int d = ei_load(ei, (long long)EE + e, is64);
    atomicAdd(&g_cnt[d], 1);
}
__global__ void scan1_kernel() {
    __shared__ int s[256];
    int i = blockIdx.x * 256 + threadIdx.x;
    int c = (i < NN) ? g_cnt[i] : 0;
    s[threadIdx.x] = c;
    __syncthreads();
#pragma unroll
    for (int o = 1; o < 256; o <<= 1) {
        int v = (threadIdx.x >= o) ? s[threadIdx.x - o] : 0;
        __syncthreads();
        s[threadIdx.x] += v;
        __syncthreads();
    }
    int incl = s[threadIdx.x];
    if (i < NN) g_off[i] = incl - c;
    if (threadIdx.x == 255) g_part[blockIdx.x] = incl;
}
__global__ void scan2_kernel() {
    __shared__ int s[512];
    int t = threadIdx.x;
    int v = (t < NBLK1) ? g_part[t] : 0;
    s[t] = v;
    __syncthreads();
#pragma unroll
    for (int o = 1; o < 512; o <<= 1) {
        int u = (t >= o) ? s[t - o] : 0;
        __syncthreads();
        s[t] += u;
        __syncthreads();
    }
    g_part2[t] = s[t] - v;
}
__global__ void scan3_kernel() {
    int i = blockIdx.x * 256 + threadIdx.x;
    if (i < NN) {
        int o = g_off[i] + g_part2[i >> 8];
        g_off[i] = o;
        g_cur[i] = o;
    }
}
__global__ void fill_kernel(const int* __restrict__ ei) {
    int e = blockIdx.x * 256 + threadIdx.x;
    bool is64 = ei_is64(ei);
    int s = ei_load(ei, e, is64);
    int d = ei_load(ei, (long long)EE + e, is64);
    int pos = atomicAdd(&g_cur[d], 1);
    g_el2[pos] = make_int2(s, e);
}

// ---------------------------------------------------------------------------
// FUSED kernel: blocks [0, AE_BLOCKS) = ae body; rest = layer-1 node GEMM.
// Independent work; the HW scheduler overlaps DRAM-bound ae with FFMA-bound
// node GEMM without extra streams. Shared buffer is a union of both layouts.
//   ae:   sEas 32x68 f (8704B) | sPt 8x68 f (2176B)
//   node: Wts 64x68 f (17408B, one 64-wide K half) | xs 16x132 f (8448B)
//         | aSs 64 f | aDs 64 f  -> 26368B total, 8 blocks/SM
// ---------------------------------------------------------------------------
__global__ void __launch_bounds__(256) fused_ae_node0_kernel(
        const float* __restrict__ edge_attr,
        const float* __restrict__ xin,
        const float* __restrict__ attS,
        const float* __restrict__ attD) {
    __shared__ __align__(16) char sbuf[26368];
    int t = threadIdx.x;

    if (blockIdx.x < AE_BLOCKS) {
        // ---------------- ae body: g_ae[e][0:8] = mean(edge_attr[e]) @ P ----
        float* sEas = (float*)sbuf;            // 32 x 68
        float* sPt = (float*)(sbuf + 8704);    // 8 x 68 (transposed P)
        const float4* __restrict__ ea4 = (const float4*)edge_attr;
        long long e0 = (long long)blockIdx.x * 32;

#pragma unroll
        for (int i = 0; i < 2; i++) {
            int idx = t + i * 256;
            sPt[(idx & 7) * 68 + (idx >> 3)] = g_P[idx];
        }
#pragma unroll
        for (int i = 0; i < 2; i++) {
            int idx = t + i * 256;           // 0..511
            int e = idx >> 4, j4 = idx & 15;
            long long base = (e0 + e) * 48;
            float4 a = ea4[base + j4];
            float4 b = ea4[base + 16 + j4];
            float4 c = ea4[base + 32 + j4];
            float4 m = make_float4((a.x + b.x + c.x) * (1.f / 3.f),
                                   (a.y + b.y + c.y) * (1.f / 3.f),
                                   (a.z + b.z + c.z) * (1.f / 3.f),
                                   (a.w + b.w + c.w) * (1.f / 3.f));
            *(float4*)&sEas[e * 68 + j4 * 4] = m;
        }
        __syncthreads();

        int e = t >> 3, h = t & 7;
        const float* er = &sEas[e * 68];
        const float* pr = &sPt[h * 68];
        float acc = 0.f;
#pragma unroll
        for (int j4 = 0; j4 < 16; j4++) {
            float4 u = *(const float4*)&er[j4 * 4];
            float4 p = *(const float4*)&pr[j4 * 4];
            acc += u.x * p.x + u.y * p.y + u.z * p.z + u.w * p.w;
        }
        g_ae[(e0 + e) * 8 + h] = acc;        // fully coalesced (edge order)
    } else {
        // ---------------- layer-1 node GEMM (IN=128), K staged in 2 halves --
        const int INp = 132;
        float* Wts = (float*)sbuf;                     // 64 x 68 (one K half)
        float* xs = (float*)(sbuf + 17408);            // 16 x 132
        float* aSs = (float*)(sbuf + 25856);
        float* aDs = (float*)(sbuf + 26112);
        int nb0 = (blockIdx.x - AE_BLOCKS) * 16;

        for (int i = t; i < 16 * 128; i += 256)
            xs[(i >> 7) * INp + (i & 127)] = xin[(size_t)nb0 * 128 + i];
        if (t < 64) { aSs[t] = attS[t]; aDs[t] = attD[t]; }

        int c = t & 63, q = t >> 6;
        u64 p0 = 0ull, p1 = 0ull, p2 = 0ull, p3 = 0ull;
#pragma unroll
        for (int half = 0; half < 2; half++) {
            __syncthreads();
            for (int i = t; i < 4096; i += 256) {
                int cc = i >> 6, kk = i & 63;
                Wts[cc * 68 + kk] = g_W1t[cc * 128 + half * 64 + kk];
            }
            __syncthreads();
            const float* wr = &Wts[c * 68];
            const float* x0 = &xs[(q * 4 + 0) * INp + half * 64];
            const float* x1 = &xs[(q * 4 + 1) * INp + half * 64];
            const float* x2 = &xs[(q * 4 + 2) * INp + half * 64];
            const float* x3 = &xs[(q * 4 + 3) * INp + half * 64];
#pragma unroll
            for (int k = 0; k < 64; k += 4) {
                ulonglong2 w  = *(const ulonglong2*)&wr[k];
                ulonglong2 u0 = *(const ulonglong2*)&x0[k];
                ulonglong2 u1 = *(const ulonglong2*)&x1[k];
                ulonglong2 u2 = *(const ulonglong2*)&x2[k];
                ulonglong2 u3 = *(const ulonglong2*)&x3[k];
                p0 = ffma2(w.x, u0.x, p0); p0 = ffma2(w.y, u0.y, p0);
                p1 = ffma2(w.x, u1.x, p1); p1 = ffma2(w.y, u1.y, p1);
                p2 = ffma2(w.x, u2.x, p2); p2 = ffma2(w.y, u2.y, p2);
                p3 = ffma2(w.x, u3.x, p3); p3 = ffma2(w.y, u3.y, p3);
            }
        }
        float av[4] = {hsum2(p0), hsum2(p1), hsum2(p2), hsum2(p3)};
        float aS = aSs[c], aD = aDs[c];
        int lane = t & 31, head = c >> 4;
        int nb = nb0 + q * 4;
#pragma unroll
        for (int j = 0; j < 4; j++) {
            g_xp[(size_t)(nb + j) * 64 + c] = av[j];
            float r1 = av[j] * aS;
            float r2 = av[j] * aD;
#pragma unroll
            for (int o = 8; o; o >>= 1) {
                r1 += __shfl_xor_sync(0xffffffffu, r1, o);
                r2 += __shfl_xor_sync(0xffffffffu, r2, o);
            }
            if ((lane & 15) == 0) {
                g_asrc[(nb + j) * 4 + head] = r1;
                g_adst[(nb + j) * 4 + head] = r2;
            }
        }
    }
}

// ---------------------------------------------------------------------------
// Gather aggregation (per layer). One warp per node; lane owns channels 2l,2l+1;
// every lane computes the softmax weight for ITS head -> no shuffles/atomics.
// ---------------------------------------------------------------------------
template <int LAYER>
__global__ void __launch_bounds__(256) gather_kernel() {
    int lane = threadIdx.x & 31;
    int n = blockIdx.x * 8 + (threadIdx.x >> 5);
    int h = lane >> 3;
    const float2* __restrict__ xp2 = (const float2*)g_xp;
    float aD = g_adst[n * 4 + h];
    int p = g_off[n], pend = g_cur[n];
    float2 acc = make_float2(0.f, 0.f);
    float den = 0.f;
#pragma unroll 4
    for (; p < pend; p++) {
        int2 se = g_el2[p];
        float a = g_asrc[se.x * 4 + h] + aD + g_ae[(size_t)se.y * 8 + LAYER * 4 + h];
        a = a > 0.f ? a : 0.2f * a;
        float w = __expf(a);
        float2 v = xp2[se.x * 32 + lane];
        acc.x += w * v.x;
        acc.y += w * v.y;
        den += w;
    }
    float inv = 1.f / fmaxf(den, 1e-16f);
    ((float2*)g_acc)[n * 32 + lane] = make_float2(acc.x * inv, acc.y * inv);
}

// ---------------------------------------------------------------------------
// Node GEMM for layer-2 / output (IN=64), register-blocked f32x2.
// WSEL selects device weight array inside device code (1=W2t, 2=Wot).
// MODE 1: in = relu(g_acc) -> g_xp + att dots; MODE 2: out = in @ W + bias
// ---------------------------------------------------------------------------
template <int MODE, int WSEL>
__global__ void __launch_bounds__(256) node_kernel(const float* __restrict__ attS,
                                                   const float* __restrict__ attD,
                                                   const float* __restrict__ bias,
                                                   float* __restrict__ outp) {
    const float* __restrict__ Wt = (WSEL == 1) ? g_W2t : g_Wot;
    const int IN = 64, INp = 68;
    __shared__ float Wts[64 * INp];
    __shared__ float xs[16 * INp];
    __shared__ float aSs[64], aDs[64];
    int t = threadIdx.x;
    for (int i = t; i < 64 * IN; i += 256) Wts[(i >> 6) * INp + (i & 63)] = Wt[i];
    if (MODE == 1 && t < 64) { aSs[t] = attS[t]; aDs[t] = attD[t]; }
    int nb0 = blockIdx.x * 16;
    for (int i = t; i < 16 * 64; i += 256)
        xs[(i >> 6) * INp + (i & 63)] = fmaxf(g_acc[(size_t)nb0 * 64 + i], 0.f);
    __syncthreads();

    int c = t & 63, q = t >> 6;
    const float* wr = &Wts[c * INp];
    const float* x0 = &xs[(q * 4 + 0) * INp];
    const float* x1 = &xs[(q * 4 + 1) * INp];
    const float* x2 = &xs[(q * 4 + 2) * INp];
    const float* x3 = &xs[(q * 4 + 3) * INp];
    u64 p0 = 0ull, p1 = 0ull, p2 = 0ull, p3 = 0ull;
#pragma unroll
    for (int k = 0; k < IN; k += 4) {
        ulonglong2 w  = *(const ulonglong2*)&wr[k];
        ulonglong2 u0 = *(const ulonglong2*)&x0[k];
        ulonglong2 u1 = *(const ulonglong2*)&x1[k];
        ulonglong2 u2 = *(const ulonglong2*)&x2[k];
        ulonglong2 u3 = *(const ulonglong2*)&x3[k];
        p0 = ffma2(w.x, u0.x, p0); p0 = ffma2(w.y, u0.y, p0);
        p1 = ffma2(w.x, u1.x, p1); p1 = ffma2(w.y, u1.y, p1);
        p2 = ffma2(w.x, u2.x, p2); p2 = ffma2(w.y, u2.y, p2);
        p3 = ffma2(w.x, u3.x, p3); p3 = ffma2(w.y, u3.y, p3);
    }
    float a0 = hsum2(p0), a1 = hsum2(p1), a2 = hsum2(p2), a3 = hsum2(p3);
    int nb = nb0 + q * 4;
    if (MODE == 2) {
        float b = bias[c];
        outp[(size_t)(nb + 0) * 64 + c] = a0 + b;
        outp[(size_t)(nb + 1) * 64 + c] = a1 + b;
        outp[(size_t)(nb + 2) * 64 + c] = a2 + b;
        outp[(size_t)(nb + 3) * 64 + c] = a3 + b;
    } else {
        float aS = aSs[c], aD = aDs[c];
        int lane = t & 31, head = c >> 4;
        float av[4] = {a0, a1, a2, a3};
#pragma unroll
        for (int j = 0; j < 4; j++) {
            g_xp[(size_t)(nb + j) * 64 + c] = av[j];
            float r1 = av[j] * aS;
            float r2 = av[j] * aD;
#pragma unroll
            for (int o = 8; o; o >>= 1) {
                r1 += __shfl_xor_sync(0xffffffffu, r1, o);
                r2 += __shfl_xor_sync(0xffffffffu, r2, o);
            }
            if ((lane & 15) == 0) {
                g_asrc[(nb + j) * 4 + head] = r1;
                g_adst[(nb + j) * 4 + head] = r2;
            }
        }
    }
}

// ---------------------------------------------------------------------------
extern "C" void kernel_launch(void* const* d_in, const int* in_sizes, int n_in,
                              void* d_out, int out_size) {
    const float* x = (const float*)d_in[0];
    const int* ei = (const int*)d_in[1];
    const float* edge_attr = (const float*)d_in[2];
    const float* W1 = (const float*)d_in[3];
    const float* We1 = (const float*)d_in[4];
    const float* as1 = (const float*)d_in[5];
    const float* ad1 = (const float*)d_in[6];
    const float* ae1 = (const float*)d_in[7];
    const float* W2 = (const float*)d_in[8];
    const float* We2 = (const float*)d_in[9];
    const float* as2 = (const float*)d_in[10];
    const float* ad2 = (const float*)d_in[11];
    const float* ae2 = (const float*)d_in[12];
    const float* Wout = (const float*)d_in[13];
    const float* bout = (const float*)d_in[14];
    float* out = (float*)d_out;

    // 1: zero_cnt + P fold + weight transpose (independent pieces, one launch)
    setup_kernel<<<NBLK1 + 1 + 32, 256>>>(We1, We2, ae1, ae2, W1, W2, Wout);
    // 2-3: start CSR build
    hist_kernel<<<EE / 256, 256>>>(ei);
    scan1_kernel<<<NBLK1, 256>>>();
    // 4: the big fused kernel (ae stream + layer-1 node GEMM overlap)
    fused_ae_node0_kernel<<<AE_BLOCKS + N0_BLOCKS, 256>>>(edge_attr, x, as1, ad1);
    // 5-7: finish CSR build
    scan2_kernel<<<1, 512>>>();
    scan3_kernel<<<NBLK1, 256>>>();
    fill_kernel<<<EE / 256, 256>>>(ei);
    // 8-11: aggregation + remaining layers
    gather_kernel<0><<<NN / 8, 256>>>();
    node_kernel<1, 1><<<NN / 16, 256>>>(as2, ad2, nullptr, nullptr);
    gather_kernel<1><<<NN / 8, 256>>>();
    node_kernel<2, 2><<<NN / 16, 256>>>(nullptr, nullptr, bout, out);
}